// round 14
// baseline (speedup 1.0000x reference)
#include <cuda_runtime.h>
#include <cstdint>
#include <cstddef>

// Problem constants
#define TT    1024
#define NSEQ  128          // B*A = 16*8
#define HH    256
#define MROWS (TT*NSEQ)    // 131072

// ---------------------------------------------------------------------------
// Scratch: precomputed input projections xr/xz/xn, each [T*NSEQ, H] fp32.
// __device__ global (allocation APIs are forbidden).
// ---------------------------------------------------------------------------
__device__ float g_X[(size_t)3 * MROWS * HH];   // ~402 MB
__device__ int   g_rst_mode;                    // 0=int32, 1=byte, 2=float32

// ---------------------------------------------------------------------------
// Detect resets storage format from the first 16384 bytes (safe under all
// three interpretations: byte buffer is exactly 16384 B; int/float are 64 KB).
//   float32 0/1 : words are 0 or 0x3F800000
//   int32   0/1 : words are 0 or 1
//   uint8   0/1 : words are 4 packed {0,1} bytes -> some non-LSB byte set
// ---------------------------------------------------------------------------
__global__ void detect_rst_kernel(const unsigned int* __restrict__ w) {
    __shared__ int s_f, s_b;
    if (threadIdx.x == 0) { s_f = 0; s_b = 0; }
    __syncthreads();
    int f = 0, b = 0;
    for (int i = threadIdx.x; i < 4096; i += 256) {
        unsigned int x = w[i];
        if (x == 0x3F800000u)          f = 1;
        else if (x & 0xFFFFFF00u)      b = 1;
    }
    if (f) s_f = 1;      // benign race: same value
    if (b) s_b = 1;
    __syncthreads();
    if (threadIdx.x == 0) g_rst_mode = s_f ? 2 : (s_b ? 1 : 0);
}

// ---------------------------------------------------------------------------
// Input projection: X[g] = ins @ W_i<g> + b_i<g>
// 128x128 tile, k-chunks of 8, 256 threads, 8x8 per thread (4+4 split in each
// dim so LDS.128 tile reads are bank-conflict-free). Grid (1024, 2, 3).
// All dims divide evenly -> no bounds checks.
// ---------------------------------------------------------------------------
__global__ __launch_bounds__(256) void proj_kernel(
    const float* __restrict__ A,
    const float* __restrict__ W0, const float* __restrict__ W1,
    const float* __restrict__ W2,
    const float* __restrict__ b0, const float* __restrict__ b1,
    const float* __restrict__ b2)
{
    const int g = blockIdx.z;
    const float* W    = (g == 0) ? W0 : (g == 1) ? W1 : W2;
    const float* bias = (g == 0) ? b0 : (g == 1) ? b1 : b2;
    float* out = g_X + (size_t)g * MROWS * HH;

    __shared__ float As[8][128];
    __shared__ float Bs[8][128];

    const int tid = threadIdx.x;
    const int bm = blockIdx.x, bn = blockIdx.y;
    const int ty = tid >> 4, tx = tid & 15;

    const float* Ap = A + ((size_t)bm * 128 + (tid >> 1)) * HH + ((tid & 1) << 2);
    const float* Wp = W + (size_t)(tid >> 5) * HH + bn * 128 + ((tid & 31) << 2);

    float acc[8][8];
    #pragma unroll
    for (int i = 0; i < 8; i++)
        #pragma unroll
        for (int j = 0; j < 8; j++) acc[i][j] = 0.f;

    for (int k0 = 0; k0 < HH; k0 += 8) {
        float4 av = *(const float4*)(Ap + k0);
        float4 bv = *(const float4*)(Wp + (size_t)k0 * HH);
        {
            int kr = (tid & 1) * 4, cc = tid >> 1;
            As[kr + 0][cc] = av.x;
            As[kr + 1][cc] = av.y;
            As[kr + 2][cc] = av.z;
            As[kr + 3][cc] = av.w;
        }
        *(float4*)&Bs[tid >> 5][(tid & 31) << 2] = bv;
        __syncthreads();
        #pragma unroll
        for (int kk = 0; kk < 8; kk++) {
            float a[8], b[8];
            *(float4*)&a[0] = *(const float4*)&As[kk][ty * 4];
            *(float4*)&a[4] = *(const float4*)&As[kk][64 + ty * 4];
            *(float4*)&b[0] = *(const float4*)&Bs[kk][tx * 4];
            *(float4*)&b[4] = *(const float4*)&Bs[kk][64 + tx * 4];
            #pragma unroll
            for (int i = 0; i < 8; i++)
                #pragma unroll
                for (int j = 0; j < 8; j++)
                    acc[i][j] = fmaf(a[i], b[j], acc[i][j]);
        }
        __syncthreads();
    }

    float bb[8];
    *(float4*)&bb[0] = *(const float4*)(bias + bn * 128 + tx * 4);
    *(float4*)&bb[4] = *(const float4*)(bias + bn * 128 + 64 + tx * 4);
    #pragma unroll
    for (int i = 0; i < 8; i++) {
        int row = (i < 4) ? (ty * 4 + i) : (64 + ty * 4 + (i - 4));
        float* op = out + ((size_t)bm * 128 + row) * HH + bn * 128;
        float4 v0, v1;
        v0.x = acc[i][0] + bb[0]; v0.y = acc[i][1] + bb[1];
        v0.z = acc[i][2] + bb[2]; v0.w = acc[i][3] + bb[3];
        v1.x = acc[i][4] + bb[4]; v1.y = acc[i][5] + bb[5];
        v1.z = acc[i][6] + bb[6]; v1.w = acc[i][7] + bb[7];
        *(float4*)(op + tx * 4)      = v0;
        *(float4*)(op + 64 + tx * 4) = v1;
    }
}

// ---------------------------------------------------------------------------
// Persistent GRU scan. 128 CTAs = 32 clusters of 4; cluster c owns sequences
// [4c, 4c+4). CTA rank r holds columns [64r, 64r+64) of W_hr/W_hz/W_hn in
// SMEM, transposed, row stride 260 floats (260%32==4, odd multiple-of-4 ->
// LDS.128 reads across 8-lane phases hit all 32 banks).
// h (4 seqs x 256) replicated per-CTA, double-buffered; new_h pushed to all
// 4 replicas via mapa + st.shared::cluster; one barrier.cluster per step
// (arrive=release, wait=acquire orders the DSMEM stores).
// Warp layout: warp w -> seq pair (w>>1), column half (w&1); each thread owns
// one column for two sequences -> 6 dot products, no cross-thread reduction.
// ---------------------------------------------------------------------------
#define WROW     260
#define SMEM_WF  (3 * 64 * WROW)                    // weight floats (49920)
#define HBUF     (4 * HH)                           // 1024 floats per h buffer
#define SMEM_BYTES ((SMEM_WF + 2 * HBUF) * 4)       // 207872 bytes

__device__ __forceinline__ float sigmoidf_(float x) {
    return 1.0f / (1.0f + __expf(-x));
}
__device__ __forceinline__ unsigned smem_u32_(const void* p) {
    unsigned r;
    asm("{ .reg .u64 t; cvta.to.shared.u64 t, %1; cvt.u32.u64 %0, t; }"
        : "=r"(r) : "l"(p));
    return r;
}
__device__ __forceinline__ void cluster_sync_() {
    asm volatile("barrier.cluster.arrive.aligned;" ::: "memory");
    asm volatile("barrier.cluster.wait.aligned;"   ::: "memory");
}
__device__ __forceinline__ void sts_cluster_(unsigned addr, float v) {
    asm volatile("st.shared::cluster.f32 [%0], %1;" :: "r"(addr), "f"(v)
                 : "memory");
}

__global__ void __cluster_dims__(4, 1, 1) __launch_bounds__(128, 1)
scan_kernel(const void* __restrict__ resets_raw,
            const float* __restrict__ h0,
            const float* __restrict__ Whr, const float* __restrict__ Whz,
            const float* __restrict__ Whn,
            const float* __restrict__ bhn,
            float* __restrict__ out)
{
    extern __shared__ float sm[];
    float* Wt = sm;                  // [3][64][WROW] (transposed slices)
    float* hb = sm + SMEM_WF;        // [2][4][HH]

    const int tid   = threadIdx.x;
    const int rank  = (int)(blockIdx.x & 3u);
    const int sbase = (int)(blockIdx.x & ~3u);   // first sequence of cluster
    const int jbase = rank * 64;

    // ---- one-time: load transposed weight slice + h0 replica ----
    {
        const float* Ws[3] = {Whr, Whz, Whn};
        #pragma unroll
        for (int g = 0; g < 3; g++) {
            const float* Wg = Ws[g] + jbase;
            for (int idx = tid; idx < HH * 64; idx += 128) {
                int k = idx >> 6, j = idx & 63;
                Wt[(g * 64 + j) * WROW + k] = Wg[(size_t)k * HH + j];
            }
        }
        for (int idx = tid; idx < HBUF; idx += 128)
            hb[idx] = h0[(size_t)sbase * HH + idx];
    }

    const int w    = tid >> 5, lane = tid & 31;
    const int p    = w >> 1;                 // sequence pair 0/1
    const int jl   = (w & 1) * 32 + lane;    // local column 0..63
    const int jglob = jbase + jl;            // global column 0..255
    const int s0l  = p * 2, s1l = p * 2 + 1; // local seqs in cluster
    const float bh = bhn[jglob];

    // DSMEM destinations (buffer 0); buffer 1 is +4096 bytes.
    unsigned la0 = smem_u32_(hb + s0l * HH + jglob);
    unsigned la1 = smem_u32_(hb + s1l * HH + jglob);
    unsigned d0[4], d1[4];
    #pragma unroll
    for (unsigned d = 0; d < 4; d++) {
        asm("mapa.shared::cluster.u32 %0, %1, %2;" : "=r"(d0[d]) : "r"(la0), "r"(d));
        asm("mapa.shared::cluster.u32 %0, %1, %2;" : "=r"(d1[d]) : "r"(la1), "r"(d));
    }

    cluster_sync_();   // weights + h0 visible cluster-wide

    const int mode = g_rst_mode;
    const int*           rst_i = (const int*)resets_raw;
    const unsigned char* rst_b = (const unsigned char*)resets_raw;
    const float*         rst_f = (const float*)resets_raw;

    const float* Xr = g_X;
    const float* Xz = g_X + (size_t)MROWS * HH;
    const float* Xn = g_X + (size_t)2 * MROWS * HH;

    size_t m0 = (size_t)(sbase + s0l) * HH + jglob;  // x/out index, seq s0
    size_t m1 = m0 + HH;                             // seq s1 = s0+1
    int cur = 0;

    for (int t = 0; t < TT; t++) {
        const int rbase = t * NSEQ + sbase;
        int rs[4];
        #pragma unroll
        for (int s = 0; s < 4; s++) {
            rs[s] = (mode == 0) ? (rst_i[rbase + s] != 0)
                  : (mode == 1) ? (rst_b[rbase + s] != 0)
                                : (rst_f[rbase + s] != 0.0f);
        }

        // issue x loads early (independent of the zeroing below)
        const float xr0 = Xr[m0], xz0 = Xz[m0], xn0 = Xn[m0];
        const float xr1 = Xr[m1], xz1 = Xz[m1], xn1 = Xn[m1];

        float* hc = hb + cur * HBUF;
        #pragma unroll
        for (int s = 0; s < 4; s++)
            if (rs[s]) { hc[s * HH + tid] = 0.f; hc[s * HH + 128 + tid] = 0.f; }
        __syncthreads();

        float ar0 = 0.f, az0 = 0.f, an0 = 0.f;
        float ar1 = 0.f, az1 = 0.f, an1 = 0.f;
        if (!(rs[s0l] && rs[s1l])) {   // warp-uniform skip: both seqs reset
            const float4* wr = (const float4*)(Wt + (size_t)jl * WROW);
            const float4* wz = (const float4*)(Wt + (size_t)(64 + jl) * WROW);
            const float4* wn = (const float4*)(Wt + (size_t)(128 + jl) * WROW);
            const float4* hu = (const float4*)(hc + s0l * HH);
            const float4* hv = (const float4*)(hc + s1l * HH);
            #pragma unroll 4
            for (int k = 0; k < HH / 4; k++) {
                float4 u = hu[k], v = hv[k];
                float4 a = wr[k];
                ar0 = fmaf(a.x, u.x, fmaf(a.y, u.y, fmaf(a.z, u.z, fmaf(a.w, u.w, ar0))));
                ar1 = fmaf(a.x, v.x, fmaf(a.y, v.y, fmaf(a.z, v.z, fmaf(a.w, v.w, ar1))));
                float4 b = wz[k];
                az0 = fmaf(b.x, u.x, fmaf(b.y, u.y, fmaf(b.z, u.z, fmaf(b.w, u.w, az0))));
                az1 = fmaf(b.x, v.x, fmaf(b.y, v.y, fmaf(b.z, v.z, fmaf(b.w, v.w, az1))));
                float4 c = wn[k];
                an0 = fmaf(c.x, u.x, fmaf(c.y, u.y, fmaf(c.z, u.z, fmaf(c.w, u.w, an0))));
                an1 = fmaf(c.x, v.x, fmaf(c.y, v.y, fmaf(c.z, v.z, fmaf(c.w, v.w, an1))));
            }
        }

        const float hold0 = hc[s0l * HH + jglob];
        const float hold1 = hc[s1l * HH + jglob];

        const float R0 = sigmoidf_(xr0 + ar0);
        const float Z0 = sigmoidf_(xz0 + az0);
        const float N0 = tanhf(xn0 + R0 * (an0 + bh));
        const float nh0 = (1.0f - Z0) * N0 + Z0 * hold0;

        const float R1 = sigmoidf_(xr1 + ar1);
        const float Z1 = sigmoidf_(xz1 + az1);
        const float N1 = tanhf(xn1 + R1 * (an1 + bh));
        const float nh1 = (1.0f - Z1) * N1 + Z1 * hold1;

        out[m0] = nh0;
        out[m1] = nh1;

        const int nxt = cur ^ 1;
        const unsigned off = (unsigned)nxt << 12;   // +4096 B for buffer 1
        #pragma unroll
        for (int d = 0; d < 4; d++) {
            sts_cluster_(d0[d] + off, nh0);
            sts_cluster_(d1[d] + off, nh1);
        }

        cluster_sync_();   // release stores / acquire for next step's reads
        cur = nxt;
        m0 += (size_t)NSEQ * HH;
        m1 += (size_t)NSEQ * HH;
    }
}

// ---------------------------------------------------------------------------
// kernel_launch: detect -> project (3 gates) -> persistent scan.
// All launches on the default stream (harness captures them); the attribute
// set is idempotent and not a stream op.
// ---------------------------------------------------------------------------
extern "C" void kernel_launch(void* const* d_in, const int* in_sizes, int n_in,
                              void* d_out, int out_size) {
    const float* ins    = (const float*)d_in[0];
    const void*  resets = d_in[1];
    const float* h0v    = (const float*)d_in[2];
    const float* W_ir   = (const float*)d_in[3];
    const float* W_iz   = (const float*)d_in[4];
    const float* W_in   = (const float*)d_in[5];
    const float* b_ir   = (const float*)d_in[6];
    const float* b_iz   = (const float*)d_in[7];
    const float* b_in   = (const float*)d_in[8];
    const float* W_hr   = (const float*)d_in[9];
    const float* W_hz   = (const float*)d_in[10];
    const float* W_hn   = (const float*)d_in[11];
    const float* b_hn   = (const float*)d_in[12];
    float* out = (float*)d_out;

    detect_rst_kernel<<<1, 256>>>((const unsigned int*)resets);

    dim3 pg(MROWS / 128, HH / 128, 3);
    proj_kernel<<<pg, 256>>>(ins, W_ir, W_iz, W_in, b_ir, b_iz, b_in);

    cudaFuncSetAttribute(scan_kernel,
                         cudaFuncAttributeMaxDynamicSharedMemorySize,
                         SMEM_BYTES);
    scan_kernel<<<NSEQ, 128, SMEM_BYTES>>>(resets, h0v,
                                           W_hr, W_hz, W_hn, b_hn, out);
}

// round 16
// speedup vs baseline: 1.1831x; 1.1831x over previous
#include <cuda_runtime.h>
#include <cstdint>
#include <cstddef>

// Problem constants
#define TT    1024
#define NSEQ  128          // B*A = 16*8
#define HH    256
#define MROWS (TT*NSEQ)    // 131072

// ---------------------------------------------------------------------------
// Scratch: precomputed input projections xr/xz/xn, each [T*NSEQ, H] fp32.
// ---------------------------------------------------------------------------
__device__ float g_X[(size_t)3 * MROWS * HH];   // ~402 MB
__device__ int   g_rst_mode;                    // 0=int32, 1=byte, 2=float32

// ---------------------------------------------------------------------------
// Detect resets storage format (unchanged from R14, known good).
// ---------------------------------------------------------------------------
__global__ void detect_rst_kernel(const unsigned int* __restrict__ w) {
    __shared__ int s_f, s_b;
    if (threadIdx.x == 0) { s_f = 0; s_b = 0; }
    __syncthreads();
    int f = 0, b = 0;
    for (int i = threadIdx.x; i < 4096; i += 256) {
        unsigned int x = w[i];
        if (x == 0x3F800000u)          f = 1;
        else if (x & 0xFFFFFF00u)      b = 1;
    }
    if (f) s_f = 1;
    if (b) s_b = 1;
    __syncthreads();
    if (threadIdx.x == 0) g_rst_mode = s_f ? 2 : (s_b ? 1 : 0);
}

// ---------------------------------------------------------------------------
// TF32 projection via mma.sync.m16n8k8 (sm_80+ ISA -> compiles at sm_103).
// X[g] = ins @ W_i<g> + b_i<g>.
// Block: 128x128 tile, 256 threads = 8 warps (2m x 4n), warp tile 64x32.
// K streamed in chunks of 32 through SMEM. Grid (MROWS/128, 2, 3).
// A smem stride 36 floats  -> fragment LDS bank == lane (conflict-free).
// W smem stride 136 floats -> 8k+n pattern covers all 32 banks.
// ---------------------------------------------------------------------------
__device__ __forceinline__ float to_tf32_(float x) {
    float r;
    asm("cvt.rna.tf32.f32 %0, %1;" : "=f"(r) : "f"(x));
    return r;
}

#define AS_STRIDE 36
#define BS_STRIDE 136

__global__ __launch_bounds__(256) void proj_mma_kernel(
    const float* __restrict__ A,
    const float* __restrict__ W0, const float* __restrict__ W1,
    const float* __restrict__ W2,
    const float* __restrict__ b0, const float* __restrict__ b1,
    const float* __restrict__ b2)
{
    __shared__ float As[128 * AS_STRIDE];   // 18432 floats
    __shared__ float Bs[32 * BS_STRIDE];    //  4352 floats

    const int g = blockIdx.z;
    const float* W    = (g == 0) ? W0 : (g == 1) ? W1 : W2;
    const float* bias = (g == 0) ? b0 : (g == 1) ? b1 : b2;
    float* out = g_X + (size_t)g * MROWS * HH;

    const int tid  = threadIdx.x;
    const int wid  = tid >> 5, lane = tid & 31;
    const int bm   = blockIdx.x;
    const int n0   = blockIdx.y * 128;
    const int wm   = (wid >> 2) * 64;       // warp m offset in tile
    const int wn   = (wid & 3) * 32;        // warp n offset in tile
    const int gq   = lane >> 2;             // group id 0..7
    const int tq   = lane & 3;              // thread-in-group 0..3

    const float* Ab = A + (size_t)bm * 128 * HH;

    float acc[4][4][4];
    #pragma unroll
    for (int i = 0; i < 4; i++)
        #pragma unroll
        for (int j = 0; j < 4; j++)
            #pragma unroll
            for (int r = 0; r < 4; r++) acc[i][j][r] = 0.f;

    for (int k0 = 0; k0 < HH; k0 += 32) {
        // ---- load A chunk [128 m][32 k] ----
        #pragma unroll
        for (int i = 0; i < 4; i++) {
            int idx = tid + i * 256;              // 0..1023 float4 slots
            int row = idx >> 3, c4 = (idx & 7) * 4;
            float4 v = *(const float4*)(Ab + (size_t)row * HH + k0 + c4);
            v.x = to_tf32_(v.x); v.y = to_tf32_(v.y);
            v.z = to_tf32_(v.z); v.w = to_tf32_(v.w);
            *(float4*)&As[row * AS_STRIDE + c4] = v;
        }
        // ---- load W chunk [32 k][128 n] ----
        #pragma unroll
        for (int i = 0; i < 4; i++) {
            int idx = tid + i * 256;
            int k = idx >> 5, n4 = (idx & 31) * 4;
            float4 v = *(const float4*)(W + (size_t)(k0 + k) * HH + n0 + n4);
            v.x = to_tf32_(v.x); v.y = to_tf32_(v.y);
            v.z = to_tf32_(v.z); v.w = to_tf32_(v.w);
            *(float4*)&Bs[k * BS_STRIDE + n4] = v;
        }
        __syncthreads();

        #pragma unroll
        for (int ks = 0; ks < 4; ks++) {
            const int kk = ks * 8;
            uint32_t a[4][4], bf[4][2];
            #pragma unroll
            for (int fm = 0; fm < 4; fm++) {
                const float* ap = &As[(wm + fm * 16 + gq) * AS_STRIDE + kk + tq];
                a[fm][0] = __float_as_uint(ap[0]);
                a[fm][1] = __float_as_uint(ap[8 * AS_STRIDE]);
                a[fm][2] = __float_as_uint(ap[4]);
                a[fm][3] = __float_as_uint(ap[8 * AS_STRIDE + 4]);
            }
            #pragma unroll
            for (int fn = 0; fn < 4; fn++) {
                const float* bp = &Bs[(kk + tq) * BS_STRIDE + wn + fn * 8 + gq];
                bf[fn][0] = __float_as_uint(bp[0]);
                bf[fn][1] = __float_as_uint(bp[4 * BS_STRIDE]);
            }
            #pragma unroll
            for (int fm = 0; fm < 4; fm++)
                #pragma unroll
                for (int fn = 0; fn < 4; fn++) {
                    asm volatile(
                        "mma.sync.aligned.m16n8k8.row.col.f32.tf32.tf32.f32 "
                        "{%0,%1,%2,%3}, {%4,%5,%6,%7}, {%8,%9}, {%0,%1,%2,%3};"
                        : "+f"(acc[fm][fn][0]), "+f"(acc[fm][fn][1]),
                          "+f"(acc[fm][fn][2]), "+f"(acc[fm][fn][3])
                        : "r"(a[fm][0]), "r"(a[fm][1]),
                          "r"(a[fm][2]), "r"(a[fm][3]),
                          "r"(bf[fn][0]), "r"(bf[fn][1]));
                }
        }
        __syncthreads();
    }

    // ---- epilogue: + bias, store fp32 ----
    #pragma unroll
    for (int fn = 0; fn < 4; fn++) {
        const int col = n0 + wn + fn * 8 + tq * 2;
        const float2 bb = *(const float2*)(bias + col);
        #pragma unroll
        for (int fm = 0; fm < 4; fm++) {
            const int r0 = bm * 128 + wm + fm * 16 + gq;
            float2 v0, v1;
            v0.x = acc[fm][fn][0] + bb.x; v0.y = acc[fm][fn][1] + bb.y;
            v1.x = acc[fm][fn][2] + bb.x; v1.y = acc[fm][fn][3] + bb.y;
            *(float2*)(out + (size_t)r0 * HH + col)       = v0;
            *(float2*)(out + (size_t)(r0 + 8) * HH + col) = v1;
        }
    }
}

// ---------------------------------------------------------------------------
// Persistent GRU scan (UNCHANGED from R14 — known correct).
// ---------------------------------------------------------------------------
#define WROW     260
#define SMEM_WF  (3 * 64 * WROW)
#define HBUF     (4 * HH)
#define SMEM_BYTES ((SMEM_WF + 2 * HBUF) * 4)

__device__ __forceinline__ float sigmoidf_(float x) {
    return 1.0f / (1.0f + __expf(-x));
}
__device__ __forceinline__ unsigned smem_u32_(const void* p) {
    unsigned r;
    asm("{ .reg .u64 t; cvta.to.shared.u64 t, %1; cvt.u32.u64 %0, t; }"
        : "=r"(r) : "l"(p));
    return r;
}
__device__ __forceinline__ void cluster_sync_() {
    asm volatile("barrier.cluster.arrive.aligned;" ::: "memory");
    asm volatile("barrier.cluster.wait.aligned;"   ::: "memory");
}
__device__ __forceinline__ void sts_cluster_(unsigned addr, float v) {
    asm volatile("st.shared::cluster.f32 [%0], %1;" :: "r"(addr), "f"(v)
                 : "memory");
}

__global__ void __cluster_dims__(4, 1, 1) __launch_bounds__(128, 1)
scan_kernel(const void* __restrict__ resets_raw,
            const float* __restrict__ h0,
            const float* __restrict__ Whr, const float* __restrict__ Whz,
            const float* __restrict__ Whn,
            const float* __restrict__ bhn,
            float* __restrict__ out)
{
    extern __shared__ float sm[];
    float* Wt = sm;
    float* hb = sm + SMEM_WF;

    const int tid   = threadIdx.x;
    const int rank  = (int)(blockIdx.x & 3u);
    const int sbase = (int)(blockIdx.x & ~3u);
    const int jbase = rank * 64;

    {
        const float* Ws[3] = {Whr, Whz, Whn};
        #pragma unroll
        for (int g = 0; g < 3; g++) {
            const float* Wg = Ws[g] + jbase;
            for (int idx = tid; idx < HH * 64; idx += 128) {
                int k = idx >> 6, j = idx & 63;
                Wt[(g * 64 + j) * WROW + k] = Wg[(size_t)k * HH + j];
            }
        }
        for (int idx = tid; idx < HBUF; idx += 128)
            hb[idx] = h0[(size_t)sbase * HH + idx];
    }

    const int w    = tid >> 5, lane = tid & 31;
    const int p    = w >> 1;
    const int jl   = (w & 1) * 32 + lane;
    const int jglob = jbase + jl;
    const int s0l  = p * 2, s1l = p * 2 + 1;
    const float bh = bhn[jglob];

    unsigned la0 = smem_u32_(hb + s0l * HH + jglob);
    unsigned la1 = smem_u32_(hb + s1l * HH + jglob);
    unsigned d0[4], d1[4];
    #pragma unroll
    for (unsigned d = 0; d < 4; d++) {
        asm("mapa.shared::cluster.u32 %0, %1, %2;" : "=r"(d0[d]) : "r"(la0), "r"(d));
        asm("mapa.shared::cluster.u32 %0, %1, %2;" : "=r"(d1[d]) : "r"(la1), "r"(d));
    }

    cluster_sync_();

    const int mode = g_rst_mode;
    const int*           rst_i = (const int*)resets_raw;
    const unsigned char* rst_b = (const unsigned char*)resets_raw;
    const float*         rst_f = (const float*)resets_raw;

    const float* Xr = g_X;
    const float* Xz = g_X + (size_t)MROWS * HH;
    const float* Xn = g_X + (size_t)2 * MROWS * HH;

    size_t m0 = (size_t)(sbase + s0l) * HH + jglob;
    size_t m1 = m0 + HH;
    int cur = 0;

    for (int t = 0; t < TT; t++) {
        const int rbase = t * NSEQ + sbase;
        int rs[4];
        #pragma unroll
        for (int s = 0; s < 4; s++) {
            rs[s] = (mode == 0) ? (rst_i[rbase + s] != 0)
                  : (mode == 1) ? (rst_b[rbase + s] != 0)
                                : (rst_f[rbase + s] != 0.0f);
        }

        const float xr0 = Xr[m0], xz0 = Xz[m0], xn0 = Xn[m0];
        const float xr1 = Xr[m1], xz1 = Xz[m1], xn1 = Xn[m1];

        float* hc = hb + cur * HBUF;
        #pragma unroll
        for (int s = 0; s < 4; s++)
            if (rs[s]) { hc[s * HH + tid] = 0.f; hc[s * HH + 128 + tid] = 0.f; }
        __syncthreads();

        float ar0 = 0.f, az0 = 0.f, an0 = 0.f;
        float ar1 = 0.f, az1 = 0.f, an1 = 0.f;
        if (!(rs[s0l] && rs[s1l])) {
            const float4* wr = (const float4*)(Wt + (size_t)jl * WROW);
            const float4* wz = (const float4*)(Wt + (size_t)(64 + jl) * WROW);
            const float4* wn = (const float4*)(Wt + (size_t)(128 + jl) * WROW);
            const float4* hu = (const float4*)(hc + s0l * HH);
            const float4* hv = (const float4*)(hc + s1l * HH);
            #pragma unroll 4
            for (int k = 0; k < HH / 4; k++) {
                float4 u = hu[k], v = hv[k];
                float4 a = wr[k];
                ar0 = fmaf(a.x, u.x, fmaf(a.y, u.y, fmaf(a.z, u.z, fmaf(a.w, u.w, ar0))));
                ar1 = fmaf(a.x, v.x, fmaf(a.y, v.y, fmaf(a.z, v.z, fmaf(a.w, v.w, ar1))));
                float4 b = wz[k];
                az0 = fmaf(b.x, u.x, fmaf(b.y, u.y, fmaf(b.z, u.z, fmaf(b.w, u.w, az0))));
                az1 = fmaf(b.x, v.x, fmaf(b.y, v.y, fmaf(b.z, v.z, fmaf(b.w, v.w, az1))));
                float4 c = wn[k];
                an0 = fmaf(c.x, u.x, fmaf(c.y, u.y, fmaf(c.z, u.z, fmaf(c.w, u.w, an0))));
                an1 = fmaf(c.x, v.x, fmaf(c.y, v.y, fmaf(c.z, v.z, fmaf(c.w, v.w, an1))));
            }
        }

        const float hold0 = hc[s0l * HH + jglob];
        const float hold1 = hc[s1l * HH + jglob];

        const float R0 = sigmoidf_(xr0 + ar0);
        const float Z0 = sigmoidf_(xz0 + az0);
        const float N0 = tanhf(xn0 + R0 * (an0 + bh));
        const float nh0 = (1.0f - Z0) * N0 + Z0 * hold0;

        const float R1 = sigmoidf_(xr1 + ar1);
        const float Z1 = sigmoidf_(xz1 + az1);
        const float N1 = tanhf(xn1 + R1 * (an1 + bh));
        const float nh1 = (1.0f - Z1) * N1 + Z1 * hold1;

        out[m0] = nh0;
        out[m1] = nh1;

        const int nxt = cur ^ 1;
        const unsigned off = (unsigned)nxt << 12;
        #pragma unroll
        for (int d = 0; d < 4; d++) {
            sts_cluster_(d0[d] + off, nh0);
            sts_cluster_(d1[d] + off, nh1);
        }

        cluster_sync_();
        cur = nxt;
        m0 += (size_t)NSEQ * HH;
        m1 += (size_t)NSEQ * HH;
    }
}

// ---------------------------------------------------------------------------
// kernel_launch: detect -> tf32 mma.sync projection -> persistent scan.
// ---------------------------------------------------------------------------
extern "C" void kernel_launch(void* const* d_in, const int* in_sizes, int n_in,
                              void* d_out, int out_size) {
    const float* ins    = (const float*)d_in[0];
    const void*  resets = d_in[1];
    const float* h0v    = (const float*)d_in[2];
    const float* W_ir   = (const float*)d_in[3];
    const float* W_iz   = (const float*)d_in[4];
    const float* W_in   = (const float*)d_in[5];
    const float* b_ir   = (const float*)d_in[6];
    const float* b_iz   = (const float*)d_in[7];
    const float* b_in   = (const float*)d_in[8];
    const float* W_hr   = (const float*)d_in[9];
    const float* W_hz   = (const float*)d_in[10];
    const float* W_hn   = (const float*)d_in[11];
    const float* b_hn   = (const float*)d_in[12];
    float* out = (float*)d_out;

    detect_rst_kernel<<<1, 256>>>((const unsigned int*)resets);

    dim3 pg(MROWS / 128, HH / 128, 3);
    proj_mma_kernel<<<pg, 256>>>(ins, W_ir, W_iz, W_in, b_ir, b_iz, b_in);

    cudaFuncSetAttribute(scan_kernel,
                         cudaFuncAttributeMaxDynamicSharedMemorySize,
                         SMEM_BYTES);
    scan_kernel<<<NSEQ, 128, SMEM_BYTES>>>(resets, h0v,
                                           W_hr, W_hz, W_hn, b_hn, out);
}

// round 17
// speedup vs baseline: 1.3679x; 1.1562x over previous
#include <cuda_runtime.h>
#include <cstdint>
#include <cstddef>

// Problem constants
#define TT    1024
#define NSEQ  128          // B*A = 16*8
#define HH    256
#define MROWS (TT*NSEQ)    // 131072

// ---------------------------------------------------------------------------
// Scratch: precomputed input projections xr/xz/xn, each [T*NSEQ, H] fp32.
// ---------------------------------------------------------------------------
__device__ float g_X[(size_t)3 * MROWS * HH];   // ~402 MB
__device__ int   g_rst_mode;                    // 0=int32, 1=byte, 2=float32

// ---------------------------------------------------------------------------
// Detect resets storage format (unchanged, known good).
// ---------------------------------------------------------------------------
__global__ void detect_rst_kernel(const unsigned int* __restrict__ w) {
    __shared__ int s_f, s_b;
    if (threadIdx.x == 0) { s_f = 0; s_b = 0; }
    __syncthreads();
    int f = 0, b = 0;
    for (int i = threadIdx.x; i < 4096; i += 256) {
        unsigned int x = w[i];
        if (x == 0x3F800000u)          f = 1;
        else if (x & 0xFFFFFF00u)      b = 1;
    }
    if (f) s_f = 1;
    if (b) s_b = 1;
    __syncthreads();
    if (threadIdx.x == 0) g_rst_mode = s_f ? 2 : (s_b ? 1 : 0);
}

// ---------------------------------------------------------------------------
// TF32 projection via mma.sync.m16n8k8 (UNCHANGED from R16 — passing).
// ---------------------------------------------------------------------------
__device__ __forceinline__ float to_tf32_(float x) {
    float r;
    asm("cvt.rna.tf32.f32 %0, %1;" : "=f"(r) : "f"(x));
    return r;
}

#define AS_STRIDE 36
#define BS_STRIDE 136

__global__ __launch_bounds__(256) void proj_mma_kernel(
    const float* __restrict__ A,
    const float* __restrict__ W0, const float* __restrict__ W1,
    const float* __restrict__ W2,
    const float* __restrict__ b0, const float* __restrict__ b1,
    const float* __restrict__ b2)
{
    __shared__ float As[128 * AS_STRIDE];
    __shared__ float Bs[32 * BS_STRIDE];

    const int g = blockIdx.z;
    const float* W    = (g == 0) ? W0 : (g == 1) ? W1 : W2;
    const float* bias = (g == 0) ? b0 : (g == 1) ? b1 : b2;
    float* out = g_X + (size_t)g * MROWS * HH;

    const int tid  = threadIdx.x;
    const int wid  = tid >> 5, lane = tid & 31;
    const int bm   = blockIdx.x;
    const int n0   = blockIdx.y * 128;
    const int wm   = (wid >> 2) * 64;
    const int wn   = (wid & 3) * 32;
    const int gq   = lane >> 2;
    const int tq   = lane & 3;

    const float* Ab = A + (size_t)bm * 128 * HH;

    float acc[4][4][4];
    #pragma unroll
    for (int i = 0; i < 4; i++)
        #pragma unroll
        for (int j = 0; j < 4; j++)
            #pragma unroll
            for (int r = 0; r < 4; r++) acc[i][j][r] = 0.f;

    for (int k0 = 0; k0 < HH; k0 += 32) {
        #pragma unroll
        for (int i = 0; i < 4; i++) {
            int idx = tid + i * 256;
            int row = idx >> 3, c4 = (idx & 7) * 4;
            float4 v = *(const float4*)(Ab + (size_t)row * HH + k0 + c4);
            v.x = to_tf32_(v.x); v.y = to_tf32_(v.y);
            v.z = to_tf32_(v.z); v.w = to_tf32_(v.w);
            *(float4*)&As[row * AS_STRIDE + c4] = v;
        }
        #pragma unroll
        for (int i = 0; i < 4; i++) {
            int idx = tid + i * 256;
            int k = idx >> 5, n4 = (idx & 31) * 4;
            float4 v = *(const float4*)(W + (size_t)(k0 + k) * HH + n0 + n4);
            v.x = to_tf32_(v.x); v.y = to_tf32_(v.y);
            v.z = to_tf32_(v.z); v.w = to_tf32_(v.w);
            *(float4*)&Bs[k * BS_STRIDE + n4] = v;
        }
        __syncthreads();

        #pragma unroll
        for (int ks = 0; ks < 4; ks++) {
            const int kk = ks * 8;
            uint32_t a[4][4], bf[4][2];
            #pragma unroll
            for (int fm = 0; fm < 4; fm++) {
                const float* ap = &As[(wm + fm * 16 + gq) * AS_STRIDE + kk + tq];
                a[fm][0] = __float_as_uint(ap[0]);
                a[fm][1] = __float_as_uint(ap[8 * AS_STRIDE]);
                a[fm][2] = __float_as_uint(ap[4]);
                a[fm][3] = __float_as_uint(ap[8 * AS_STRIDE + 4]);
            }
            #pragma unroll
            for (int fn = 0; fn < 4; fn++) {
                const float* bp = &Bs[(kk + tq) * BS_STRIDE + wn + fn * 8 + gq];
                bf[fn][0] = __float_as_uint(bp[0]);
                bf[fn][1] = __float_as_uint(bp[4 * BS_STRIDE]);
            }
            #pragma unroll
            for (int fm = 0; fm < 4; fm++)
                #pragma unroll
                for (int fn = 0; fn < 4; fn++) {
                    asm volatile(
                        "mma.sync.aligned.m16n8k8.row.col.f32.tf32.tf32.f32 "
                        "{%0,%1,%2,%3}, {%4,%5,%6,%7}, {%8,%9}, {%0,%1,%2,%3};"
                        : "+f"(acc[fm][fn][0]), "+f"(acc[fm][fn][1]),
                          "+f"(acc[fm][fn][2]), "+f"(acc[fm][fn][3])
                        : "r"(a[fm][0]), "r"(a[fm][1]),
                          "r"(a[fm][2]), "r"(a[fm][3]),
                          "r"(bf[fn][0]), "r"(bf[fn][1]));
                }
        }
        __syncthreads();
    }

    #pragma unroll
    for (int fn = 0; fn < 4; fn++) {
        const int col = n0 + wn + fn * 8 + tq * 2;
        const float2 bb = *(const float2*)(bias + col);
        #pragma unroll
        for (int fm = 0; fm < 4; fm++) {
            const int r0 = bm * 128 + wm + fm * 16 + gq;
            float2 v0, v1;
            v0.x = acc[fm][fn][0] + bb.x; v0.y = acc[fm][fn][1] + bb.y;
            v1.x = acc[fm][fn][2] + bb.x; v1.y = acc[fm][fn][3] + bb.y;
            *(float2*)(out + (size_t)r0 * HH + col)       = v0;
            *(float2*)(out + (size_t)(r0 + 8) * HH + col) = v1;
        }
    }
}

// ---------------------------------------------------------------------------
// Persistent GRU scan v2.
// Thread = (column jl = tid&63, k-half kh = tid>>6). Each weight element is
// read ONCE per CTA per step; partials pair-reduced via smem. CTA-uniform
// reset mask selects a 2-seq loop (p=11/16), 4-seq loop (p=5/16), or skip.
// ---------------------------------------------------------------------------
#define WROW     260
#define SMEM_WF  (3 * 64 * WROW)                 // 49920 floats
#define HBUF     (4 * HH)                        // 1024 floats per buffer
#define RED_OFF  (SMEM_WF + 2 * HBUF)            // reduction scratch offset
#define RED_FLOATS (64 * 12)
#define SMEM_BYTES ((RED_OFF + RED_FLOATS) * 4)  // 210944 bytes

__device__ __forceinline__ float sigmoidf_(float x) {
    return 1.0f / (1.0f + __expf(-x));
}
__device__ __forceinline__ unsigned smem_u32_(const void* p) {
    unsigned r;
    asm("{ .reg .u64 t; cvta.to.shared.u64 t, %1; cvt.u32.u64 %0, t; }"
        : "=r"(r) : "l"(p));
    return r;
}
__device__ __forceinline__ void cluster_sync_() {
    asm volatile("barrier.cluster.arrive.aligned;" ::: "memory");
    asm volatile("barrier.cluster.wait.aligned;"   ::: "memory");
}
__device__ __forceinline__ void sts_cluster_(unsigned addr, float v) {
    asm volatile("st.shared::cluster.f32 [%0], %1;" :: "r"(addr), "f"(v)
                 : "memory");
}

__global__ void __cluster_dims__(4, 1, 1) __launch_bounds__(128, 1)
scan_kernel(const void* __restrict__ resets_raw,
            const float* __restrict__ h0,
            const float* __restrict__ Whr, const float* __restrict__ Whz,
            const float* __restrict__ Whn,
            const float* __restrict__ bhn,
            float* __restrict__ out)
{
    extern __shared__ float sm[];
    float* Wt  = sm;                 // [3][64][WROW] transposed slices
    float* hb  = sm + SMEM_WF;       // [2][4][HH]
    float* red = sm + RED_OFF;       // [64][12] pair-reduction scratch

    const int tid   = threadIdx.x;
    const int rank  = (int)(blockIdx.x & 3u);
    const int sbase = (int)(blockIdx.x & ~3u);
    const int jbase = rank * 64;

    // ---- one-time: transposed weight slice + h0 replica ----
    {
        const float* Ws[3] = {Whr, Whz, Whn};
        #pragma unroll
        for (int g = 0; g < 3; g++) {
            const float* Wg = Ws[g] + jbase;
            for (int idx = tid; idx < HH * 64; idx += 128) {
                int k = idx >> 6, j = idx & 63;
                Wt[(g * 64 + j) * WROW + k] = Wg[(size_t)k * HH + j];
            }
        }
        for (int idx = tid; idx < HBUF; idx += 128)
            hb[idx] = h0[(size_t)sbase * HH + idx];
    }

    const int jl    = tid & 63;        // column within slice
    const int kh    = tid >> 6;        // k-half 0/1 (warp-uniform)
    const int jglob = jbase + jl;
    const int kbase = kh * 128;
    const float bh  = bhn[jglob];

    // DSMEM destinations for buffer 0; buffer 1 = +4096 bytes.
    unsigned dst[4][4];
    #pragma unroll
    for (int s = 0; s < 4; s++) {
        unsigned la = smem_u32_(hb + s * HH + jglob);
        #pragma unroll
        for (unsigned d = 0; d < 4; d++)
            asm("mapa.shared::cluster.u32 %0, %1, %2;"
                : "=r"(dst[s][d]) : "r"(la), "r"(d));
    }

    cluster_sync_();   // weights + h0 visible cluster-wide

    const int mode = g_rst_mode;
    const int*           rst_i = (const int*)resets_raw;
    const unsigned char* rst_b = (const unsigned char*)resets_raw;
    const float*         rst_f = (const float*)resets_raw;

    const float* Xr = g_X;
    const float* Xz = g_X + (size_t)MROWS * HH;
    const float* Xn = g_X + (size_t)2 * MROWS * HH;

    size_t mrow[4];
    #pragma unroll
    for (int s = 0; s < 4; s++)
        mrow[s] = (size_t)(sbase + s) * HH + jglob;

    const float* wr = Wt + (size_t)jl * WROW + kbase;
    const float* wz = Wt + (size_t)(64 + jl) * WROW + kbase;
    const float* wn = Wt + (size_t)(128 + jl) * WROW + kbase;

    size_t off = 0;
    int cur = 0;

    for (int t = 0; t < TT; t++) {
        const int rbase = t * NSEQ + sbase;
        int rs[4];
        #pragma unroll
        for (int s = 0; s < 4; s++) {
            rs[s] = (mode == 0) ? (rst_i[rbase + s] != 0)
                  : (mode == 1) ? (rst_b[rbase + s] != 0)
                                : (rst_f[rbase + s] != 0.0f);
        }

        // x loads (kh==0 half only; overlap DRAM latency with the matvec)
        float xr[4], xz[4], xn[4];
        if (kh == 0) {
            #pragma unroll
            for (int s = 0; s < 4; s++) {
                const size_t m = off + mrow[s];
                xr[s] = Xr[m]; xz[s] = Xz[m]; xn[s] = Xn[m];
            }
        }

        float* hc = hb + cur * HBUF;
        #pragma unroll
        for (int s = 0; s < 4; s++)
            if (rs[s]) { hc[s * HH + tid] = 0.f; hc[s * HH + 128 + tid] = 0.f; }
        __syncthreads();

        // partials: p[s*3 + {r,z,n}] over k-range [kbase, kbase+128)
        float p[12];
        #pragma unroll
        for (int i = 0; i < 12; i++) p[i] = 0.f;

        const int amask = (~(rs[0] | (rs[1] << 1) | (rs[2] << 2) | (rs[3] << 3))) & 15;
        const int na = __popc(amask);

        if (na > 0) {
            if (na <= 2) {
                const int i0 = __ffs(amask) - 1;
                const int m2 = amask & (amask - 1);
                const int i1 = m2 ? (__ffs(m2) - 1) : i0;
                const float4* hu = (const float4*)(hc + i0 * HH + kbase);
                const float4* hv = (const float4*)(hc + i1 * HH + kbase);
                const float4* ar4 = (const float4*)wr;
                const float4* az4 = (const float4*)wz;
                const float4* an4 = (const float4*)wn;
                float q[6];
                #pragma unroll
                for (int i = 0; i < 6; i++) q[i] = 0.f;
                #pragma unroll 4
                for (int k = 0; k < 32; k++) {
                    float4 u = hu[k], v = hv[k];
                    float4 a = ar4[k];
                    q[0] = fmaf(a.x, u.x, fmaf(a.y, u.y, fmaf(a.z, u.z, fmaf(a.w, u.w, q[0]))));
                    q[3] = fmaf(a.x, v.x, fmaf(a.y, v.y, fmaf(a.z, v.z, fmaf(a.w, v.w, q[3]))));
                    float4 b = az4[k];
                    q[1] = fmaf(b.x, u.x, fmaf(b.y, u.y, fmaf(b.z, u.z, fmaf(b.w, u.w, q[1]))));
                    q[4] = fmaf(b.x, v.x, fmaf(b.y, v.y, fmaf(b.z, v.z, fmaf(b.w, v.w, q[4]))));
                    float4 c = an4[k];
                    q[2] = fmaf(c.x, u.x, fmaf(c.y, u.y, fmaf(c.z, u.z, fmaf(c.w, u.w, q[2]))));
                    q[5] = fmaf(c.x, v.x, fmaf(c.y, v.y, fmaf(c.z, v.z, fmaf(c.w, v.w, q[5]))));
                }
                #pragma unroll
                for (int s = 0; s < 4; s++) {
                    const bool c0 = (s == i0);
                    const bool c1 = (m2 != 0) && (s == i1);
                    p[s * 3 + 0] = c0 ? q[0] : (c1 ? q[3] : 0.f);
                    p[s * 3 + 1] = c0 ? q[1] : (c1 ? q[4] : 0.f);
                    p[s * 3 + 2] = c0 ? q[2] : (c1 ? q[5] : 0.f);
                }
            } else {
                // 3-4 active: process all 4 (reset seqs have h==0 -> add 0)
                const float4* h0p = (const float4*)(hc + 0 * HH + kbase);
                const float4* h1p = (const float4*)(hc + 1 * HH + kbase);
                const float4* h2p = (const float4*)(hc + 2 * HH + kbase);
                const float4* h3p = (const float4*)(hc + 3 * HH + kbase);
                const float4* ar4 = (const float4*)wr;
                const float4* az4 = (const float4*)wz;
                const float4* an4 = (const float4*)wn;
                #pragma unroll 4
                for (int k = 0; k < 32; k++) {
                    float4 u0 = h0p[k], u1 = h1p[k], u2 = h2p[k], u3 = h3p[k];
                    float4 a = ar4[k];
                    p[0]  = fmaf(a.x, u0.x, fmaf(a.y, u0.y, fmaf(a.z, u0.z, fmaf(a.w, u0.w, p[0]))));
                    p[3]  = fmaf(a.x, u1.x, fmaf(a.y, u1.y, fmaf(a.z, u1.z, fmaf(a.w, u1.w, p[3]))));
                    p[6]  = fmaf(a.x, u2.x, fmaf(a.y, u2.y, fmaf(a.z, u2.z, fmaf(a.w, u2.w, p[6]))));
                    p[9]  = fmaf(a.x, u3.x, fmaf(a.y, u3.y, fmaf(a.z, u3.z, fmaf(a.w, u3.w, p[9]))));
                    float4 b = az4[k];
                    p[1]  = fmaf(b.x, u0.x, fmaf(b.y, u0.y, fmaf(b.z, u0.z, fmaf(b.w, u0.w, p[1]))));
                    p[4]  = fmaf(b.x, u1.x, fmaf(b.y, u1.y, fmaf(b.z, u1.z, fmaf(b.w, u1.w, p[4]))));
                    p[7]  = fmaf(b.x, u2.x, fmaf(b.y, u2.y, fmaf(b.z, u2.z, fmaf(b.w, u2.w, p[7]))));
                    p[10] = fmaf(b.x, u3.x, fmaf(b.y, u3.y, fmaf(b.z, u3.z, fmaf(b.w, u3.w, p[10]))));
                    float4 c = an4[k];
                    p[2]  = fmaf(c.x, u0.x, fmaf(c.y, u0.y, fmaf(c.z, u0.z, fmaf(c.w, u0.w, p[2]))));
                    p[5]  = fmaf(c.x, u1.x, fmaf(c.y, u1.y, fmaf(c.z, u1.z, fmaf(c.w, u1.w, p[5]))));
                    p[8]  = fmaf(c.x, u2.x, fmaf(c.y, u2.y, fmaf(c.z, u2.z, fmaf(c.w, u2.w, p[8]))));
                    p[11] = fmaf(c.x, u3.x, fmaf(c.y, u3.y, fmaf(c.z, u3.z, fmaf(c.w, u3.w, p[11]))));
                }
            }
        }

        // pair reduction: kh==1 stores partials, kh==0 adds them
        if (kh == 1) {
            float4* r4 = (float4*)(red + jl * 12);
            r4[0] = make_float4(p[0], p[1], p[2],  p[3]);
            r4[1] = make_float4(p[4], p[5], p[6],  p[7]);
            r4[2] = make_float4(p[8], p[9], p[10], p[11]);
        }
        __syncthreads();

        const int nxt = cur ^ 1;
        if (kh == 0) {
            const float4* r4 = (const float4*)(red + jl * 12);
            float4 r0 = r4[0], r1 = r4[1], r2 = r4[2];
            p[0] += r0.x; p[1] += r0.y; p[2]  += r0.z; p[3] += r0.w;
            p[4] += r1.x; p[5] += r1.y; p[6]  += r1.z; p[7] += r1.w;
            p[8] += r2.x; p[9] += r2.y; p[10] += r2.z; p[11] += r2.w;

            const unsigned boff = (unsigned)nxt << 12;   // buffer offset bytes
            #pragma unroll
            for (int s = 0; s < 4; s++) {
                const float hold = hc[s * HH + jglob];
                const float R  = sigmoidf_(xr[s] + p[s * 3 + 0]);
                const float Z  = sigmoidf_(xz[s] + p[s * 3 + 1]);
                const float N  = tanhf(xn[s] + R * (p[s * 3 + 2] + bh));
                const float nh = (1.0f - Z) * N + Z * hold;
                out[off + mrow[s]] = nh;
                #pragma unroll
                for (int d = 0; d < 4; d++)
                    sts_cluster_(dst[s][d] + boff, nh);
            }
        }

        cluster_sync_();   // release our DSMEM stores / acquire peers'
        cur = nxt;
        off += (size_t)NSEQ * HH;
    }
}

// ---------------------------------------------------------------------------
// kernel_launch: detect -> tf32 mma.sync projection -> persistent scan v2.
// ---------------------------------------------------------------------------
extern "C" void kernel_launch(void* const* d_in, const int* in_sizes, int n_in,
                              void* d_out, int out_size) {
    const float* ins    = (const float*)d_in[0];
    const void*  resets = d_in[1];
    const float* h0v    = (const float*)d_in[2];
    const float* W_ir   = (const float*)d_in[3];
    const float* W_iz   = (const float*)d_in[4];
    const float* W_in   = (const float*)d_in[5];
    const float* b_ir   = (const float*)d_in[6];
    const float* b_iz   = (const float*)d_in[7];
    const float* b_in   = (const float*)d_in[8];
    const float* W_hr   = (const float*)d_in[9];
    const float* W_hz   = (const float*)d_in[10];
    const float* W_hn   = (const float*)d_in[11];
    const float* b_hn   = (const float*)d_in[12];
    float* out = (float*)d_out;

    detect_rst_kernel<<<1, 256>>>((const unsigned int*)resets);

    dim3 pg(MROWS / 128, HH / 128, 3);
    proj_mma_kernel<<<pg, 256>>>(ins, W_ir, W_iz, W_in, b_ir, b_iz, b_in);

    cudaFuncSetAttribute(scan_kernel,
                         cudaFuncAttributeMaxDynamicSharedMemorySize,
                         SMEM_BYTES);
    scan_kernel<<<NSEQ, 128, SMEM_BYTES>>>(resets, h0v,
                                           W_hr, W_hz, W_hn, b_hn, out);
}